// round 1
// baseline (speedup 1.0000x reference)
#include <cuda_runtime.h>
#include <cuda_bf16.h>

// Problem constants
#define HW      7744        // 88*88
#define HW4     1936        // HW / 4 (float4 units)
#define NR      8192        // 32*256 rows
#define MSL     10          // memory slots
#define NCHUNK  4           // split-K chunks over HW
#define CHUNK4  484         // float4 per chunk (1936 floats)
#define TPB     256
#define HWL     64          // hw lanes per row-group
#define RG      4           // row groups per block (256/64)
#define RT      4           // rows per thread
#define RPB     (RG*RT)     // 16 rows per block
#define SMEM_BYTES (MSL*CHUNK4*16)   // 77440 B: mem tile as ulonglong2[10][484]

// Deterministic scratch (no atomics): partial scores + softmaxed scores
__device__ float g_Spart[NCHUNK][NR][MSL];
__device__ float g_Ssoft[NR][MSL];

// ---- packed f32x2 helpers (Blackwell) ----
__device__ __forceinline__ unsigned long long pk(float lo, float hi) {
    unsigned long long r;
    asm("mov.b64 %0,{%1,%2};" : "=l"(r) : "f"(lo), "f"(hi));
    return r;
}
__device__ __forceinline__ void upk(unsigned long long v, float& lo, float& hi) {
    asm("mov.b64 {%0,%1},%2;" : "=f"(lo), "=f"(hi) : "l"(v));
}
__device__ __forceinline__ void ffma2(unsigned long long& d, unsigned long long a, unsigned long long b) {
    asm("fma.rn.f32x2 %0, %1, %2, %0;" : "+l"(d) : "l"(a), "l"(b));
}

// ============================================================================
// Kernel 1: partial scores  Spart[c][r][m] = sum_{hw in chunk c} x[r,hw]*mem[m,hw]
// Block: (chunk, rowgroup). mem chunk staged in smem, reused by 16 rows.
// ============================================================================
__global__ __launch_bounds__(TPB, 2)
void score_kernel(const float* __restrict__ x, const float* __restrict__ mem) {
    extern __shared__ ulonglong2 smem[];   // [MSL][CHUNK4]

    const int chunk   = blockIdx.x;
    const int rowBase = blockIdx.y * RPB;
    const int tid     = threadIdx.x;

    // Stage mem[10, chunk] into smem (float4 == ulonglong2, layout-compatible with f32x2)
    const ulonglong2* gm = reinterpret_cast<const ulonglong2*>(mem);
    for (int i = tid; i < MSL * CHUNK4; i += TPB) {
        int m = i / CHUNK4, i4 = i - m * CHUNK4;
        smem[i] = gm[(size_t)m * HW4 + (size_t)chunk * CHUNK4 + i4];
    }
    __syncthreads();

    const int l = tid & (HWL - 1);   // hw lane 0..63
    const int g = tid >> 6;          // row group 0..3

    unsigned long long acc[RT][MSL];
    #pragma unroll
    for (int j = 0; j < RT; j++)
        #pragma unroll
        for (int m = 0; m < MSL; m++) acc[j][m] = 0ull;

    const ulonglong2* gx = reinterpret_cast<const ulonglong2*>(x);
    const size_t cOff = (size_t)chunk * CHUNK4;

    for (int i4 = l; i4 < CHUNK4; i4 += HWL) {
        unsigned long long xlo[RT], xhi[RT];
        #pragma unroll
        for (int j = 0; j < RT; j++) {
            ulonglong2 v = gx[(size_t)(rowBase + g * RT + j) * HW4 + cOff + i4];
            xlo[j] = v.x; xhi[j] = v.y;
        }
        #pragma unroll
        for (int m = 0; m < MSL; m++) {
            ulonglong2 mv = smem[m * CHUNK4 + i4];
            #pragma unroll
            for (int j = 0; j < RT; j++) {
                ffma2(acc[j][m], xlo[j], mv.x);
                ffma2(acc[j][m], xhi[j], mv.y);
            }
        }
    }

    // Reduce: horizontal f32x2 add, warp butterfly, then pair-of-warps combine
    __shared__ float red[TPB / 32][RT * MSL];
    const int warp = tid >> 5, lane = tid & 31;
    #pragma unroll
    for (int j = 0; j < RT; j++) {
        #pragma unroll
        for (int m = 0; m < MSL; m++) {
            float lo, hi; upk(acc[j][m], lo, hi);
            float s = lo + hi;
            #pragma unroll
            for (int off = 16; off; off >>= 1)
                s += __shfl_xor_sync(0xffffffffu, s, off);
            if (lane == 0) red[warp][j * MSL + m] = s;
        }
    }
    __syncthreads();

    if (tid < RPB * MSL) {
        int rl = tid / MSL, m = tid - rl * MSL;
        int gg = rl / RT, jj = rl - gg * RT;
        // warps 2*gg and 2*gg+1 belong to row group gg
        float v = red[2 * gg][jj * MSL + m] + red[2 * gg + 1][jj * MSL + m];
        g_Spart[chunk][rowBase + rl][m] = v;
    }
}

// ============================================================================
// Kernel 2: reduce split-K partials + softmax over m (one thread per row)
// ============================================================================
__global__ void softmax_kernel() {
    int r = blockIdx.x * blockDim.x + threadIdx.x;
    if (r >= NR) return;
    float sc[MSL];
    #pragma unroll
    for (int m = 0; m < MSL; m++) sc[m] = g_Spart[0][r][m];
    #pragma unroll
    for (int c = 1; c < NCHUNK; c++)
        #pragma unroll
        for (int m = 0; m < MSL; m++) sc[m] += g_Spart[c][r][m];

    float mx = sc[0];
    #pragma unroll
    for (int m = 1; m < MSL; m++) mx = fmaxf(mx, sc[m]);
    float sum = 0.f;
    #pragma unroll
    for (int m = 0; m < MSL; m++) { sc[m] = __expf(sc[m] - mx); sum += sc[m]; }
    float inv = 1.f / sum;
    #pragma unroll
    for (int m = 0; m < MSL; m++) g_Ssoft[r][m] = sc[m] * inv;
}

// ============================================================================
// Kernel 3: value[r,hw] = sum_m Ssoft[r,m] * mem[m,hw]
// Same tiling as kernel 1; softmax weights register-cached as (s,s) f32x2.
// ============================================================================
__global__ __launch_bounds__(TPB, 2)
void value_kernel(const float* __restrict__ mem, float* __restrict__ out) {
    extern __shared__ ulonglong2 smem[];   // [MSL][CHUNK4]

    const int chunk   = blockIdx.x;
    const int rowBase = blockIdx.y * RPB;
    const int tid     = threadIdx.x;

    const ulonglong2* gm = reinterpret_cast<const ulonglong2*>(mem);
    for (int i = tid; i < MSL * CHUNK4; i += TPB) {
        int m = i / CHUNK4, i4 = i - m * CHUNK4;
        smem[i] = gm[(size_t)m * HW4 + (size_t)chunk * CHUNK4 + i4];
    }
    __syncthreads();

    const int l = tid & (HWL - 1);
    const int g = tid >> 6;

    // Replicated softmax weights for my RT rows
    unsigned long long s2[RT][MSL];
    #pragma unroll
    for (int j = 0; j < RT; j++) {
        const float* sp = &g_Ssoft[rowBase + g * RT + j][0];
        #pragma unroll
        for (int m = 0; m < MSL; m++) { float v = sp[m]; s2[j][m] = pk(v, v); }
    }

    ulonglong2* gout = reinterpret_cast<ulonglong2*>(out);
    const size_t cOff = (size_t)chunk * CHUNK4;

    for (int i4 = l; i4 < CHUNK4; i4 += HWL) {
        unsigned long long alo[RT], ahi[RT];
        #pragma unroll
        for (int j = 0; j < RT; j++) { alo[j] = 0ull; ahi[j] = 0ull; }
        #pragma unroll
        for (int m = 0; m < MSL; m++) {
            ulonglong2 mv = smem[m * CHUNK4 + i4];
            #pragma unroll
            for (int j = 0; j < RT; j++) {
                ffma2(alo[j], s2[j][m], mv.x);
                ffma2(ahi[j], s2[j][m], mv.y);
            }
        }
        #pragma unroll
        for (int j = 0; j < RT; j++) {
            ulonglong2 o; o.x = alo[j]; o.y = ahi[j];
            gout[(size_t)(rowBase + g * RT + j) * HW4 + cOff + i4] = o;
        }
    }
}

// ============================================================================
extern "C" void kernel_launch(void* const* d_in, const int* in_sizes, int n_in,
                              void* d_out, int out_size) {
    // Defensive input ordering: mem has 77440 elements, x has 15,859,712
    const float* x;
    const float* mem;
    if (in_sizes[0] == MSL * HW) { mem = (const float*)d_in[0]; x = (const float*)d_in[1]; }
    else                         { x   = (const float*)d_in[0]; mem = (const float*)d_in[1]; }
    float* out = (float*)d_out;

    cudaFuncSetAttribute(score_kernel, cudaFuncAttributeMaxDynamicSharedMemorySize, SMEM_BYTES);
    cudaFuncSetAttribute(value_kernel, cudaFuncAttributeMaxDynamicSharedMemorySize, SMEM_BYTES);

    dim3 grid(NCHUNK, NR / RPB);   // (4, 512)
    score_kernel<<<grid, TPB, SMEM_BYTES>>>(x, mem);
    softmax_kernel<<<NR / TPB, TPB>>>();
    value_kernel<<<grid, TPB, SMEM_BYTES>>>(mem, out);
}

// round 3
// speedup vs baseline: 1.2445x; 1.2445x over previous
#include <cuda_runtime.h>
#include <cuda_bf16.h>

// Problem constants
#define HW      7744        // 88*88
#define HW4     1936        // HW / 4 (float4 units)
#define NR      8192        // 32*256 rows
#define MSL     10          // memory slots
#define NCHUNK  8           // split-K chunks over HW
#define CHUNK4  242         // float4 per chunk (968 floats)
#define TPB     256
#define HWL     32          // hw lanes per row-group (one warp)
#define RG      8           // row groups per block (warps)
#define RT      2           // rows per thread
#define RPB     (RG*RT)     // 16 rows per block
#define SC_SMEM (MSL*CHUNK4*16)   // 38720 B mem tile (ulonglong2[10][242])

// Value kernel tiling
#define VTILES  61          // ceil(1936/32)
#define VROWS   128         // rows per value block

// Deterministic scratch (no atomics)
__device__ float g_Spart[NCHUNK][NR][MSL];
__device__ float g_Ssoft[NR][MSL];

// ---- packed f32x2 helpers ----
__device__ __forceinline__ unsigned long long pk(float lo, float hi) {
    unsigned long long r;
    asm("mov.b64 %0,{%1,%2};" : "=l"(r) : "f"(lo), "f"(hi));
    return r;
}
__device__ __forceinline__ void upk(unsigned long long v, float& lo, float& hi) {
    asm("mov.b64 {%0,%1},%2;" : "=f"(lo), "=f"(hi) : "l"(v));
}
__device__ __forceinline__ void ffma2(unsigned long long& d, unsigned long long a, unsigned long long b) {
    asm("fma.rn.f32x2 %0, %1, %2, %0;" : "+l"(d) : "l"(a), "l"(b));
}

// ============================================================================
// Kernel 1: partial scores. Block = (chunk, 16 rows). Warp = 2 rows.
// mem chunk staged in smem (38.7KB), acc in 40 regs -> 4 CTAs/SM.
// ============================================================================
__global__ __launch_bounds__(TPB, 4)
void score_kernel(const float* __restrict__ x, const float* __restrict__ mem) {
    extern __shared__ ulonglong2 smem[];   // [MSL][CHUNK4]

    const int chunk   = blockIdx.x;
    const int rowBase = blockIdx.y * RPB;
    const int tid     = threadIdx.x;
    const int lane    = tid & 31;
    const int wid     = tid >> 5;

    // Stage mem[10][chunk] into smem
    const ulonglong2* gm = reinterpret_cast<const ulonglong2*>(mem);
    #pragma unroll
    for (int m = 0; m < MSL; m++) {
        if (tid < CHUNK4)
            smem[m * CHUNK4 + tid] = gm[(size_t)m * HW4 + (size_t)chunk * CHUNK4 + tid];
    }
    __syncthreads();

    // This warp's two rows
    const int r0 = rowBase + 2 * wid;
    const ulonglong2* gx0 = reinterpret_cast<const ulonglong2*>(x) + (size_t)r0 * HW4 + (size_t)chunk * CHUNK4;
    const ulonglong2* gx1 = gx0 + HW4;

    unsigned long long acc0[MSL], acc1[MSL];
    #pragma unroll
    for (int m = 0; m < MSL; m++) { acc0[m] = 0ull; acc1[m] = 0ull; }

    #pragma unroll 4
    for (int k = 0; k < 8; k++) {
        const int i4 = lane + k * HWL;
        if (i4 < CHUNK4) {
            ulonglong2 v0 = gx0[i4];
            ulonglong2 v1 = gx1[i4];
            #pragma unroll
            for (int m = 0; m < MSL; m++) {
                ulonglong2 mv = smem[m * CHUNK4 + i4];
                ffma2(acc0[m], v0.x, mv.x);
                ffma2(acc0[m], v0.y, mv.y);
                ffma2(acc1[m], v1.x, mv.x);
                ffma2(acc1[m], v1.y, mv.y);
            }
        }
    }

    // Two-row warp reduction: fold f32x2 -> xor1 -> parity select -> xor 2..16
    float t[MSL];
    #pragma unroll
    for (int m = 0; m < MSL; m++) {
        float lo, hi;
        upk(acc0[m], lo, hi); float s0 = lo + hi;
        upk(acc1[m], lo, hi); float s1 = lo + hi;
        s0 += __shfl_xor_sync(0xffffffffu, s0, 1);
        s1 += __shfl_xor_sync(0xffffffffu, s1, 1);
        t[m] = (lane & 1) ? s1 : s0;
    }
    #pragma unroll
    for (int off = 2; off <= 16; off <<= 1)
        #pragma unroll
        for (int m = 0; m < MSL; m++)
            t[m] += __shfl_xor_sync(0xffffffffu, t[m], off);

    if (lane < 2) {
        float* dst = &g_Spart[chunk][r0 + lane][0];
        #pragma unroll
        for (int m = 0; m < MSL; m++) dst[m] = t[m];
    }
}

// ============================================================================
// Kernel 2: reduce split-K partials + softmax over m (one thread per row)
// ============================================================================
__global__ void softmax_kernel() {
    int r = blockIdx.x * blockDim.x + threadIdx.x;
    if (r >= NR) return;
    float sc[MSL];
    #pragma unroll
    for (int m = 0; m < MSL; m++) sc[m] = g_Spart[0][r][m];
    #pragma unroll
    for (int c = 1; c < NCHUNK; c++)
        #pragma unroll
        for (int m = 0; m < MSL; m++) sc[m] += g_Spart[c][r][m];

    float mx = sc[0];
    #pragma unroll
    for (int m = 1; m < MSL; m++) mx = fmaxf(mx, sc[m]);
    float sum = 0.f;
    #pragma unroll
    for (int m = 0; m < MSL; m++) { sc[m] = __expf(sc[m] - mx); sum += sc[m]; }
    float inv = 1.f / sum;
    #pragma unroll
    for (int m = 0; m < MSL; m++) g_Ssoft[r][m] = sc[m] * inv;
}

// ============================================================================
// Kernel 3: value[r,hw] = sum_m Ssoft[r,m] * mem[m,hw]
// i4-outer / row-inner: each warp keeps its 32-float4 mem column in 40 regs,
// softmax weights pre-replicated (w,w) in smem, broadcast-read per row.
// Per warp-row: 20 ffma2 + 5 LDS.128 + 1 STG.128 for 512B of output.
// ============================================================================
__global__ __launch_bounds__(TPB, 4)
void value_kernel(const float* __restrict__ mem, float* __restrict__ out) {
    __shared__ unsigned long long w2[VROWS * MSL];   // (w,w) pairs, 10.2 KB

    const int tid     = threadIdx.x;
    const int lane    = tid & 31;
    const int wid     = tid >> 5;
    const int rowBase = blockIdx.y * VROWS;
    const int i4      = blockIdx.x * 32 + lane;
    const bool valid  = (i4 < HW4);

    // Stage replicated softmax weights for this block's 128 rows
    {
        const float* sp = &g_Ssoft[rowBase][0];
        #pragma unroll
        for (int k = 0; k < (VROWS * MSL) / TPB; k++) {
            int idx = tid + k * TPB;
            float v = sp[idx];
            w2[idx] = pk(v, v);
        }
    }

    // Each lane holds mem[m][i4] (float4 as 2 f32x2) in registers: 40 regs
    unsigned long long mlo[MSL], mhi[MSL];
    {
        const ulonglong2* gm = reinterpret_cast<const ulonglong2*>(mem);
        #pragma unroll
        for (int m = 0; m < MSL; m++) {
            if (valid) {
                ulonglong2 v = gm[(size_t)m * HW4 + i4];
                mlo[m] = v.x; mhi[m] = v.y;
            } else {
                mlo[m] = 0ull; mhi[m] = 0ull;
            }
        }
    }
    __syncthreads();

    ulonglong2* gout = reinterpret_cast<ulonglong2*>(out);
    const ulonglong2* wsm = reinterpret_cast<const ulonglong2*>(w2);

    // Warp w handles rows w, w+8, ..., 16 rows total
    #pragma unroll 2
    for (int k = 0; k < VROWS / RG; k++) {
        const int rl = wid + k * RG;             // local row 0..127
        // 10 replicated weights = 5 ulonglong2 broadcast loads (16B aligned: rl*80B)
        unsigned long long w[MSL];
        #pragma unroll
        for (int j = 0; j < MSL / 2; j++) {
            ulonglong2 wp = wsm[rl * (MSL / 2) + j];
            w[2 * j]     = wp.x;
            w[2 * j + 1] = wp.y;
        }
        unsigned long long alo = 0ull, ahi = 0ull;
        #pragma unroll
        for (int m = 0; m < MSL; m++) {
            ffma2(alo, w[m], mlo[m]);
            ffma2(ahi, w[m], mhi[m]);
        }
        if (valid) {
            ulonglong2 o; o.x = alo; o.y = ahi;
            gout[(size_t)(rowBase + rl) * HW4 + i4] = o;
        }
    }
}

// ============================================================================
extern "C" void kernel_launch(void* const* d_in, const int* in_sizes, int n_in,
                              void* d_out, int out_size) {
    const float* x;
    const float* mem;
    if (in_sizes[0] == MSL * HW) { mem = (const float*)d_in[0]; x = (const float*)d_in[1]; }
    else                         { x   = (const float*)d_in[0]; mem = (const float*)d_in[1]; }
    float* out = (float*)d_out;

    dim3 gridS(NCHUNK, NR / RPB);      // (8, 512)
    score_kernel<<<gridS, TPB, SC_SMEM>>>(x, mem);
    softmax_kernel<<<NR / TPB, TPB>>>();
    dim3 gridV(VTILES, NR / VROWS);    // (61, 64)
    value_kernel<<<gridV, TPB>>>(mem, out);
}

// round 5
// speedup vs baseline: 1.3352x; 1.0729x over previous
#include <cuda_runtime.h>
#include <cuda_bf16.h>

// Problem constants
#define HW      7744        // 88*88
#define HW4     1936        // HW / 4 (float4 units)
#define NR      8192        // 32*256 rows
#define MSL     10          // memory slots
#define NCHUNK  8           // split-K chunks over HW
#define CHUNK4  242         // float4 per chunk (968 floats)
#define TPB     256
#define RPB     16          // rows per block
#define MH      5           // m-slots per warp (half of MSL)
#define SC_SMEM (MSL*CHUNK4*16)   // 38720 B mem tile (ulonglong2[10][242])

// Value kernel tiling
#define VTILES  61          // ceil(1936/32)
#define VROWS   128         // rows per value block
#define VRG     8           // warps per value block

// Deterministic scratch (no atomics)
__device__ float g_Spart[NCHUNK][NR][MSL];
__device__ float g_Ssoft[NR][MSL];

// ---- packed f32x2 helpers ----
__device__ __forceinline__ unsigned long long pk(float lo, float hi) {
    unsigned long long r;
    asm("mov.b64 %0,{%1,%2};" : "=l"(r) : "f"(lo), "f"(hi));
    return r;
}
__device__ __forceinline__ void upk(unsigned long long v, float& lo, float& hi) {
    asm("mov.b64 {%0,%1},%2;" : "=f"(lo), "=f"(hi) : "l"(v));
}
__device__ __forceinline__ void ffma2(unsigned long long& d, unsigned long long a, unsigned long long b) {
    asm("fma.rn.f32x2 %0, %1, %2, %0;" : "+l"(d) : "l"(a), "l"(b));
}

// ============================================================================
// Kernel 1: partial scores. Block = (chunk, 16 rows), 8 warps.
// Warp = 4 rows x 5 m-slots (m split across warp halves): per k-iter
// 4 LDG.128 + 5 LDS.128 -> 36 wavefronts per 40 ffma2 (was 48/40).
// mg is the high warp bit so m-group 1 re-reads x lines L1-resident.
// ============================================================================
__global__ __launch_bounds__(TPB, 3)
void score_kernel(const float* __restrict__ x, const float* __restrict__ mem) {
    extern __shared__ ulonglong2 smem[];   // [MSL][CHUNK4]

    const int chunk   = blockIdx.x;
    const int rowBase = blockIdx.y * RPB;
    const int tid     = threadIdx.x;
    const int lane    = tid & 31;
    const int wid     = tid >> 5;

    // Stage mem[10][chunk] into smem
    const ulonglong2* gm = reinterpret_cast<const ulonglong2*>(mem);
    #pragma unroll
    for (int m = 0; m < MSL; m++) {
        if (tid < CHUNK4)
            smem[m * CHUNK4 + tid] = gm[(size_t)m * HW4 + (size_t)chunk * CHUNK4 + tid];
    }
    __syncthreads();

    const int mg = wid >> 2;           // m-group: slots [5*mg, 5*mg+5)
    const int rq = wid & 3;            // row quad 0..3
    const int r0 = rowBase + rq * 4;

    const ulonglong2* gx = reinterpret_cast<const ulonglong2*>(x)
                         + (size_t)r0 * HW4 + (size_t)chunk * CHUNK4;
    const ulonglong2* ms = smem + mg * MH * CHUNK4;

    unsigned long long acc[4][MH];
    #pragma unroll
    for (int j = 0; j < 4; j++)
        #pragma unroll
        for (int m = 0; m < MH; m++) acc[j][m] = 0ull;

    #pragma unroll 2
    for (int k = 0; k < 8; k++) {
        const int i4 = lane + k * 32;
        if (i4 < CHUNK4) {
            unsigned long long vlo[4], vhi[4];
            #pragma unroll
            for (int j = 0; j < 4; j++) {
                ulonglong2 v = gx[(size_t)j * HW4 + i4];
                vlo[j] = v.x; vhi[j] = v.y;
            }
            #pragma unroll
            for (int m = 0; m < MH; m++) {
                ulonglong2 mv = ms[m * CHUNK4 + i4];
                #pragma unroll
                for (int j = 0; j < 4; j++) {
                    ffma2(acc[j][m], vlo[j], mv.x);
                    ffma2(acc[j][m], vhi[j], mv.y);
                }
            }
        }
    }

    // Reduction: fold f32x2, then 3-stage parity-select butterfly.
    // Stage 1 (xor1): pair rows (0,1) and (2,3); select by lane&1.
    // Stage 2 (xor2): merge the two pairs; select by lane&2.
    // Stage 3 (xor 4,8,16): full sum; lane L holds row (L&3).
    float u[MH], w[MH];
    #pragma unroll
    for (int m = 0; m < MH; m++) {
        float lo, hi, s0, s1, s2, s3;
        upk(acc[0][m], lo, hi); s0 = lo + hi;
        upk(acc[1][m], lo, hi); s1 = lo + hi;
        upk(acc[2][m], lo, hi); s2 = lo + hi;
        upk(acc[3][m], lo, hi); s3 = lo + hi;
        s0 += __shfl_xor_sync(0xffffffffu, s0, 1);
        s1 += __shfl_xor_sync(0xffffffffu, s1, 1);
        s2 += __shfl_xor_sync(0xffffffffu, s2, 1);
        s3 += __shfl_xor_sync(0xffffffffu, s3, 1);
        u[m] = (lane & 1) ? s1 : s0;
        w[m] = (lane & 1) ? s3 : s2;
    }
    #pragma unroll
    for (int m = 0; m < MH; m++) {
        u[m] += __shfl_xor_sync(0xffffffffu, u[m], 2);
        w[m] += __shfl_xor_sync(0xffffffffu, w[m], 2);
        u[m] = (lane & 2) ? w[m] : u[m];
    }
    #pragma unroll
    for (int off = 4; off <= 16; off <<= 1)
        #pragma unroll
        for (int m = 0; m < MH; m++)
            u[m] += __shfl_xor_sync(0xffffffffu, u[m], off);

    if (lane < 4) {
        float* dst = &g_Spart[chunk][r0 + lane][mg * MH];
        #pragma unroll
        for (int m = 0; m < MH; m++) dst[m] = u[m];
    }
}

// ============================================================================
// Kernel 2: reduce split-K partials + softmax over m (one thread per row)
// ============================================================================
__global__ void softmax_kernel() {
    int r = blockIdx.x * blockDim.x + threadIdx.x;
    if (r >= NR) return;
    float sc[MSL];
    #pragma unroll
    for (int m = 0; m < MSL; m++) sc[m] = g_Spart[0][r][m];
    #pragma unroll
    for (int c = 1; c < NCHUNK; c++)
        #pragma unroll
        for (int m = 0; m < MSL; m++) sc[m] += g_Spart[c][r][m];

    float mx = sc[0];
    #pragma unroll
    for (int m = 1; m < MSL; m++) mx = fmaxf(mx, sc[m]);
    float sum = 0.f;
    #pragma unroll
    for (int m = 0; m < MSL; m++) { sc[m] = __expf(sc[m] - mx); sum += sc[m]; }
    float inv = 1.f / sum;
    #pragma unroll
    for (int m = 0; m < MSL; m++) g_Ssoft[r][m] = sc[m] * inv;
}

// ============================================================================
// Kernel 3: value[r,hw] = sum_m Ssoft[r,m] * mem[m,hw]
// i4-outer / row-inner: warp keeps its 32-float4 mem column in 40 regs,
// softmax weights pre-replicated (w,w) in smem, broadcast-read per row.
// ============================================================================
__global__ __launch_bounds__(TPB, 4)
void value_kernel(const float* __restrict__ mem, float* __restrict__ out) {
    __shared__ unsigned long long w2[VROWS * MSL];   // (w,w) pairs, 10.2 KB

    const int tid     = threadIdx.x;
    const int lane    = tid & 31;
    const int wid     = tid >> 5;
    const int rowBase = blockIdx.y * VROWS;
    const int i4      = blockIdx.x * 32 + lane;
    const bool valid  = (i4 < HW4);

    // Stage replicated softmax weights for this block's 128 rows
    {
        const float* sp = &g_Ssoft[rowBase][0];
        #pragma unroll
        for (int k = 0; k < (VROWS * MSL) / TPB; k++) {
            int idx = tid + k * TPB;
            float v = sp[idx];
            w2[idx] = pk(v, v);
        }
    }

    // Each lane holds mem[m][i4] (float4 as 2 f32x2) in registers: 40 regs
    unsigned long long mlo[MSL], mhi[MSL];
    {
        const ulonglong2* gm = reinterpret_cast<const ulonglong2*>(mem);
        #pragma unroll
        for (int m = 0; m < MSL; m++) {
            if (valid) {
                ulonglong2 v = gm[(size_t)m * HW4 + i4];
                mlo[m] = v.x; mhi[m] = v.y;
            } else {
                mlo[m] = 0ull; mhi[m] = 0ull;
            }
        }
    }
    __syncthreads();

    ulonglong2* gout = reinterpret_cast<ulonglong2*>(out);
    const ulonglong2* wsm = reinterpret_cast<const ulonglong2*>(w2);

    // Warp w handles rows w, w+8, ..., 16 rows total
    #pragma unroll 2
    for (int k = 0; k < VROWS / VRG; k++) {
        const int rl = wid + k * VRG;            // local row 0..127
        unsigned long long w[MSL];
        #pragma unroll
        for (int j = 0; j < MSL / 2; j++) {
            ulonglong2 wp = wsm[rl * (MSL / 2) + j];
            w[2 * j]     = wp.x;
            w[2 * j + 1] = wp.y;
        }
        unsigned long long alo = 0ull, ahi = 0ull;
        #pragma unroll
        for (int m = 0; m < MSL; m++) {
            ffma2(alo, w[m], mlo[m]);
            ffma2(ahi, w[m], mhi[m]);
        }
        if (valid) {
            ulonglong2 o; o.x = alo; o.y = ahi;
            gout[(size_t)(rowBase + rl) * HW4 + i4] = o;
        }
    }
}

// ============================================================================
extern "C" void kernel_launch(void* const* d_in, const int* in_sizes, int n_in,
                              void* d_out, int out_size) {
    const float* x;
    const float* mem;
    if (in_sizes[0] == MSL * HW) { mem = (const float*)d_in[0]; x = (const float*)d_in[1]; }
    else                         { x   = (const float*)d_in[0]; mem = (const float*)d_in[1]; }
    float* out = (float*)d_out;

    dim3 gridS(NCHUNK, NR / RPB);      // (8, 512)
    score_kernel<<<gridS, TPB, SC_SMEM>>>(x, mem);
    softmax_kernel<<<NR / TPB, TPB>>>();
    dim3 gridV(VTILES, NR / VROWS);    // (61, 64)
    value_kernel<<<gridV, TPB>>>(mem, out);
}